// round 1
// baseline (speedup 1.0000x reference)
#include <cuda_runtime.h>
#include <cfloat>

#define NUM_U 100000
#define NUM_I 50000
#define NUM_E 1000000
#define NUM_B 250000
#define DIM   64
#define DIM2  128
#define NTOT  (NUM_U + NUM_I)          // 150000
#define MSG_EPS 1e-7f
#define BN_EPS  1e-5f
#define SCAN_NB ((NTOT + 1023) / 1024) // 147

// ---------------- device scratch (static, allocation-free) ----------------
__device__ int g_deg[NTOT];
__device__ int g_cur[NTOT];
__device__ int g_rowptr[NTOT + 1];
__device__ int g_bsum[256];
__device__ int g_sorted[2 * NUM_E];
__device__ __align__(16) float g_z[NUM_U * DIM];
__device__ __align__(16) float g_h[NUM_U * DIM2];
__device__ __align__(16) float g_fu[2][NUM_U * DIM];
__device__ __align__(16) float g_fi[2][NUM_I * DIM];
__device__ float g_sum[DIM2];
__device__ float g_ssq[DIM2];
__device__ float g_scale[DIM2];
__device__ float g_shift[DIM2];

// ---------------- CSR build ----------------
__global__ void zero_kernel() {
    int i = blockIdx.x * blockDim.x + threadIdx.x;
    if (i < NTOT) { g_deg[i] = 0; g_cur[i] = 0; }
}

__global__ void hist_kernel(const int* __restrict__ edge) {
    int e = blockIdx.x * blockDim.x + threadIdx.x;
    if (e >= NUM_E) return;
    int u = edge[e];
    int it = edge[NUM_E + e];
    atomicAdd(&g_deg[it], 1);           // items: dst of user->item
    atomicAdd(&g_deg[NUM_I + u], 1);    // users: dst of item->user
}

__global__ void scan1_kernel() {
    __shared__ int s[1024];
    int i = blockIdx.x * 1024 + threadIdx.x;
    int v = (i < NTOT) ? g_deg[i] : 0;
    s[threadIdx.x] = v;
    __syncthreads();
    for (int off = 1; off < 1024; off <<= 1) {
        int t = (threadIdx.x >= off) ? s[threadIdx.x - off] : 0;
        __syncthreads();
        s[threadIdx.x] += t;
        __syncthreads();
    }
    if (i < NTOT) g_rowptr[i] = s[threadIdx.x] - v;   // block-local exclusive
    if (threadIdx.x == 1023) g_bsum[blockIdx.x] = s[1023];
}

__global__ void scan2_kernel() {
    int run = 0;
    for (int b = 0; b < SCAN_NB; b++) { int t = g_bsum[b]; g_bsum[b] = run; run += t; }
}

__global__ void scan3_kernel() {
    int i = blockIdx.x * 1024 + threadIdx.x;
    if (i < NTOT) g_rowptr[i] += g_bsum[i >> 10];
    if (blockIdx.x == 0 && threadIdx.x == 0) g_rowptr[NTOT] = 2 * NUM_E;
}

__global__ void scatter_kernel(const int* __restrict__ edge) {
    int e = blockIdx.x * blockDim.x + threadIdx.x;
    if (e >= NUM_E) return;
    int u = edge[e];
    int it = edge[NUM_E + e];
    int p1 = g_rowptr[it] + atomicAdd(&g_cur[it], 1);
    g_sorted[p1] = u;                                  // src users, grouped by item
    int p2 = g_rowptr[NUM_I + u] + atomicAdd(&g_cur[NUM_I + u], 1);
    g_sorted[p2] = it;                                 // src items, grouped by user
}

// ---------------- softmax aggregation (online, one pass) ----------------
// one warp per dst node; lane owns channels 2*lane, 2*lane+1
__global__ void agg_kernel(const float* __restrict__ xsrc,
                           const float* __restrict__ xdst,
                           int base, int ndst) {
    int warp = threadIdx.x >> 5;
    int node = blockIdx.x * 8 + warp;
    if (node >= ndst) return;
    int lane = threadIdx.x & 31;
    int beg = g_rowptr[base + node];
    int end = g_rowptr[base + node + 1];

    float M0 = -FLT_MAX, M1 = -FLT_MAX;
    float S0 = 0.f, S1 = 0.f, A0 = 0.f, A1 = 0.f;
    const float2* xs = (const float2*)xsrc;

    float2 v;
    if (beg < end) {
        int s0 = g_sorted[beg];
        v = xs[(size_t)s0 * 32 + lane];
    }
    for (int e = beg; e < end; e++) {
        float2 vc = v;
        if (e + 1 < end) {
            int sn = g_sorted[e + 1];
            v = xs[(size_t)sn * 32 + lane];   // prefetch next row
        }
        float m0 = fmaxf(vc.x, 0.f) + MSG_EPS;
        float m1 = fmaxf(vc.y, 0.f) + MSG_EPS;
        if (m0 > M0) { float r = __expf(M0 - m0); S0 = S0 * r + 1.f; A0 = A0 * r + m0; M0 = m0; }
        else         { float t = __expf(m0 - M0); S0 += t; A0 += t * m0; }
        if (m1 > M1) { float r = __expf(M1 - m1); S1 = S1 * r + 1.f; A1 = A1 * r + m1; M1 = m1; }
        else         { float t = __expf(m1 - M1); S1 += t; A1 += t * m1; }
    }
    float2 xd = ((const float2*)xdst)[(size_t)node * 32 + lane];
    float2 o;
    o.x = ((S0 > 0.f) ? A0 / S0 : 0.f) + xd.x;
    o.y = ((S1 > 0.f) ? A1 / S1 : 0.f) + xd.y;
    ((float2*)g_z)[(size_t)node * 32 + lane] = o;
}

// ---------------- BN stats reset + finalize ----------------
__global__ void zstat_kernel() {
    int t = threadIdx.x;
    g_sum[t] = 0.f; g_ssq[t] = 0.f;
}

__global__ void stats_kernel(const float* __restrict__ gam,
                             const float* __restrict__ bet, float invN) {
    int c = threadIdx.x;
    float mu  = g_sum[c] * invN;
    float var = fmaxf(g_ssq[c] * invN - mu * mu, 0.f);
    float sc  = gam[c] * rsqrtf(var + BN_EPS);
    g_scale[c] = sc;
    g_shift[c] = bet[c] - mu * sc;
}

// ---------------- GEMM1: h = z @ W1 + b1  (+ per-channel sum/sumsq) ----------------
// 128 threads, 64-row x 128-col tile, 8x8 microtile (cols strided by 16)
__global__ void gemm1_kernel(const float* __restrict__ W1p,
                             const float* __restrict__ b1p, int N) {
    extern __shared__ float smem[];
    float* ws   = smem;                  // 64*128
    float* zs   = smem + DIM * DIM2;     // 64*65 (pad 65 -> conflict-free)
    float* sbuf = zs + 64 * 65;          // 128
    float* qbuf = sbuf + DIM2;           // 128
    int tid = threadIdx.x;
    int R0 = blockIdx.x * 64;

    for (int i = tid; i < DIM * DIM2 / 4; i += 128)
        ((float4*)ws)[i] = ((const float4*)W1p)[i];
    for (int i = tid; i < 64 * 16; i += 128) {
        int r = i >> 4, c4 = i & 15;
        float4 v = make_float4(0.f, 0.f, 0.f, 0.f);
        int row = R0 + r;
        if (row < N) v = ((const float4*)g_z)[row * 16 + c4];
        zs[r * 65 + c4 * 4 + 0] = v.x;
        zs[r * 65 + c4 * 4 + 1] = v.y;
        zs[r * 65 + c4 * 4 + 2] = v.z;
        zs[r * 65 + c4 * 4 + 3] = v.w;
    }
    __syncthreads();

    int tx = tid & 15, ty = tid >> 4;
    float acc[8][8];
#pragma unroll
    for (int i = 0; i < 8; i++)
#pragma unroll
        for (int j = 0; j < 8; j++) acc[i][j] = 0.f;

#pragma unroll 4
    for (int k = 0; k < DIM; k++) {
        float a[8], w[8];
#pragma unroll
        for (int i = 0; i < 8; i++) a[i] = zs[(ty * 8 + i) * 65 + k];
#pragma unroll
        for (int j = 0; j < 8; j++) w[j] = ws[k * DIM2 + tx + 16 * j];
#pragma unroll
        for (int i = 0; i < 8; i++)
#pragma unroll
            for (int j = 0; j < 8; j++) acc[i][j] = fmaf(a[i], w[j], acc[i][j]);
    }

    float bb[8];
#pragma unroll
    for (int j = 0; j < 8; j++) bb[j] = b1p[tx + 16 * j];

    sbuf[tid] = 0.f; qbuf[tid] = 0.f;
    __syncthreads();
#pragma unroll
    for (int j = 0; j < 8; j++) {
        int c = tx + 16 * j;
        float s = 0.f, q = 0.f;
#pragma unroll
        for (int i = 0; i < 8; i++) {
            int row = R0 + ty * 8 + i;
            if (row < N) {
                float h = acc[i][j] + bb[j];
                g_h[(size_t)row * DIM2 + c] = h;
                s += h; q += h * h;
            }
        }
        atomicAdd(&sbuf[c], s);
        atomicAdd(&qbuf[c], q);
    }
    __syncthreads();
    atomicAdd(&g_sum[tid], sbuf[tid]);
    atomicAdd(&g_ssq[tid], qbuf[tid]);
}

// ---------------- GEMM2: out = relu( relu(scale*h+shift) @ W2 + b2 ) ----------------
// 128 threads, 64-row x 64-col tile, 8x4 microtile
__global__ void gemm2_kernel(const float* __restrict__ W2p,
                             const float* __restrict__ b2p,
                             float* __restrict__ outp, int N) {
    extern __shared__ float smem[];
    float* ws  = smem;                   // 128*64
    float* hs  = smem + DIM2 * DIM;      // 64*133 (pad 133 -> conflict-free)
    float* ssc = hs + 64 * 133;          // 128
    float* ssh = ssc + DIM2;             // 128
    int tid = threadIdx.x;
    int R0 = blockIdx.x * 64;

    ssc[tid] = g_scale[tid];
    ssh[tid] = g_shift[tid];
    __syncthreads();

    for (int i = tid; i < DIM2 * DIM / 4; i += 128)
        ((float4*)ws)[i] = ((const float4*)W2p)[i];
    for (int i = tid; i < 64 * 32; i += 128) {
        int r = i >> 5, k4 = i & 31;
        float4 v = make_float4(0.f, 0.f, 0.f, 0.f);
        int row = R0 + r;
        if (row < N) v = ((const float4*)g_h)[(size_t)row * 32 + k4];
        int k = k4 * 4;
        hs[r * 133 + k + 0] = fmaxf(fmaf(v.x, ssc[k + 0], ssh[k + 0]), 0.f);
        hs[r * 133 + k + 1] = fmaxf(fmaf(v.y, ssc[k + 1], ssh[k + 1]), 0.f);
        hs[r * 133 + k + 2] = fmaxf(fmaf(v.z, ssc[k + 2], ssh[k + 2]), 0.f);
        hs[r * 133 + k + 3] = fmaxf(fmaf(v.w, ssc[k + 3], ssh[k + 3]), 0.f);
    }
    __syncthreads();

    int tx = tid & 15, ty = tid >> 4;
    float acc[8][4];
#pragma unroll
    for (int i = 0; i < 8; i++)
#pragma unroll
        for (int j = 0; j < 4; j++) acc[i][j] = 0.f;

#pragma unroll 4
    for (int k = 0; k < DIM2; k++) {
        float a[8], w[4];
#pragma unroll
        for (int i = 0; i < 8; i++) a[i] = hs[(ty * 8 + i) * 133 + k];
#pragma unroll
        for (int j = 0; j < 4; j++) w[j] = ws[k * DIM + tx + 16 * j];
#pragma unroll
        for (int i = 0; i < 8; i++)
#pragma unroll
            for (int j = 0; j < 4; j++) acc[i][j] = fmaf(a[i], w[j], acc[i][j]);
    }

    float bb[4];
#pragma unroll
    for (int j = 0; j < 4; j++) bb[j] = b2p[tx + 16 * j];
#pragma unroll
    for (int i = 0; i < 8; i++) {
        int row = R0 + ty * 8 + i;
        if (row < N) {
#pragma unroll
            for (int j = 0; j < 4; j++)
                outp[(size_t)row * DIM + tx + 16 * j] = fmaxf(acc[i][j] + bb[j], 0.f);
        }
    }
}

// ---------------- decoder: dot product over supervision edges ----------------
__global__ void dec_kernel(const float* __restrict__ fu,
                           const float* __restrict__ fi,
                           const int* __restrict__ pe,
                           float* __restrict__ out) {
    int w = (blockIdx.x * blockDim.x + threadIdx.x) >> 5;
    if (w >= NUM_B) return;
    int lane = threadIdx.x & 31;
    int pu = pe[w];
    int pi = pe[NUM_B + w];
    float2 a = ((const float2*)fu)[(size_t)pu * 32 + lane];
    float2 c = ((const float2*)fi)[(size_t)pi * 32 + lane];
    float s = a.x * c.x + a.y * c.y;
#pragma unroll
    for (int off = 16; off > 0; off >>= 1)
        s += __shfl_xor_sync(0xFFFFFFFFu, s, off);
    if (lane == 0) out[w] = s;
}

// ---------------- host ----------------
extern "C" void kernel_launch(void* const* d_in, const int* in_sizes, int n_in,
                              void* d_out, int out_size) {
    const float* x_user = (const float*)d_in[0];
    const float* x_item = (const float*)d_in[1];
    const float* W1     = (const float*)d_in[2];
    const float* b1     = (const float*)d_in[3];
    const float* gam    = (const float*)d_in[4];
    const float* bet    = (const float*)d_in[5];
    const float* W2     = (const float*)d_in[6];
    const float* b2     = (const float*)d_in[7];
    const int*   edge   = (const int*)d_in[8];
    const int*   pred   = (const int*)d_in[9];
    float*       out    = (float*)d_out;

    const int SM1 = (DIM * DIM2 + 64 * 65 + 2 * DIM2) * 4;        // 50432 B
    const int SM2 = (DIM2 * DIM + 64 * 133 + 2 * DIM2) * 4;       // 67840 B
    cudaFuncSetAttribute(gemm1_kernel, cudaFuncAttributeMaxDynamicSharedMemorySize, SM1);
    cudaFuncSetAttribute(gemm2_kernel, cudaFuncAttributeMaxDynamicSharedMemorySize, SM2);

    float *fu0, *fi0;
    cudaGetSymbolAddress((void**)&fu0, g_fu);
    cudaGetSymbolAddress((void**)&fi0, g_fi);
    float* fu1 = fu0 + (size_t)NUM_U * DIM;
    float* fi1 = fi0 + (size_t)NUM_I * DIM;

    // CSR build (graph fixed across layers)
    zero_kernel<<<(NTOT + 255) / 256, 256>>>();
    hist_kernel<<<(NUM_E + 255) / 256, 256>>>(edge);
    scan1_kernel<<<SCAN_NB, 1024>>>();
    scan2_kernel<<<1, 1>>>();
    scan3_kernel<<<SCAN_NB, 1024>>>();
    scatter_kernel<<<(NUM_E + 255) / 256, 256>>>(edge);

    const float* xu_in = x_user;
    const float* xi_in = x_item;
    for (int l = 0; l < 3; l++) {
        float* xu_out = (l & 1) ? fu1 : fu0;
        float* xi_out = (l & 1) ? fi1 : fi0;

        // conv user->item (et=0), dst = items
        {
            int et = l * 2 + 0;
            agg_kernel<<<(NUM_I + 7) / 8, 256>>>(xu_in, xi_in, 0, NUM_I);
            zstat_kernel<<<1, 128>>>();
            gemm1_kernel<<<(NUM_I + 63) / 64, 128, SM1>>>(W1 + (size_t)et * DIM * DIM2,
                                                          b1 + (size_t)et * DIM2, NUM_I);
            stats_kernel<<<1, 128>>>(gam + (size_t)et * DIM2, bet + (size_t)et * DIM2,
                                     1.0f / NUM_I);
            gemm2_kernel<<<(NUM_I + 63) / 64, 128, SM2>>>(W2 + (size_t)et * DIM2 * DIM,
                                                          b2 + (size_t)et * DIM, xi_out, NUM_I);
        }
        // conv item->user (et=1), dst = users
        {
            int et = l * 2 + 1;
            agg_kernel<<<(NUM_U + 7) / 8, 256>>>(xi_in, xu_in, NUM_I, NUM_U);
            zstat_kernel<<<1, 128>>>();
            gemm1_kernel<<<(NUM_U + 63) / 64, 128, SM1>>>(W1 + (size_t)et * DIM * DIM2,
                                                          b1 + (size_t)et * DIM2, NUM_U);
            stats_kernel<<<1, 128>>>(gam + (size_t)et * DIM2, bet + (size_t)et * DIM2,
                                     1.0f / NUM_U);
            gemm2_kernel<<<(NUM_U + 63) / 64, 128, SM2>>>(W2 + (size_t)et * DIM2 * DIM,
                                                          b2 + (size_t)et * DIM, xu_out, NUM_U);
        }
        xu_in = xu_out;
        xi_in = xi_out;
    }

    dec_kernel<<<(NUM_B + 7) / 8, 256>>>(xu_in, xi_in, pred, out);
}

// round 2
// speedup vs baseline: 1.4406x; 1.4406x over previous
#include <cuda_runtime.h>
#include <cfloat>

typedef unsigned long long ull;

#define NUM_U 100000
#define NUM_I 50000
#define NUM_E 1000000
#define NUM_B 250000
#define DIM   64
#define DIM2  128
#define NTOT  (NUM_U + NUM_I)          // 150000
#define MSG_EPS 1e-7f
#define BN_EPS  1e-5f
#define SCAN_NB ((NTOT + 1023) / 1024) // 147

// ---------------- device scratch (static, allocation-free) ----------------
__device__ int g_deg[NTOT];
__device__ int g_cur[NTOT];
__device__ int g_rowptr[NTOT + 1];
__device__ int g_bsum[256];
__device__ int g_sorted[2 * NUM_E];
__device__ __align__(16) float g_z[NUM_U * DIM];
__device__ __align__(16) float g_h[NUM_U * DIM2];
__device__ __align__(16) float g_fu[2][NUM_U * DIM];
__device__ __align__(16) float g_fi[2][NUM_I * DIM];
__device__ float g_sum[DIM2];
__device__ float g_ssq[DIM2];
__device__ float g_scale[DIM2];
__device__ float g_shift[DIM2];

// ---------------- packed f32x2 helpers (sm_103a FFMA2 path) ----------------
__device__ __forceinline__ ull pack2(float x) {
    ull r; asm("mov.b64 %0, {%1, %1};" : "=l"(r) : "f"(x)); return r;
}
__device__ __forceinline__ void ffma2(ull& d, ull a, ull b) {
    asm("fma.rn.f32x2 %0, %1, %2, %0;" : "+l"(d) : "l"(a), "l"(b));
}
__device__ __forceinline__ void unpack2(ull v, float& lo, float& hi) {
    asm("mov.b64 {%0, %1}, %2;" : "=f"(lo), "=f"(hi) : "l"(v));
}

// ---------------- CSR build ----------------
__global__ void zero_kernel() {
    int i = blockIdx.x * blockDim.x + threadIdx.x;
    if (i < NTOT) { g_deg[i] = 0; g_cur[i] = 0; }
    if (i < DIM2) { g_sum[i] = 0.f; g_ssq[i] = 0.f; }
}

__global__ void hist_kernel(const int* __restrict__ edge) {
    int e = blockIdx.x * blockDim.x + threadIdx.x;
    if (e >= NUM_E) return;
    int u = edge[e];
    int it = edge[NUM_E + e];
    atomicAdd(&g_deg[it], 1);           // items: dst of user->item
    atomicAdd(&g_deg[NUM_I + u], 1);    // users: dst of item->user
}

__global__ void scan1_kernel() {
    __shared__ int s[1024];
    int i = blockIdx.x * 1024 + threadIdx.x;
    int v = (i < NTOT) ? g_deg[i] : 0;
    s[threadIdx.x] = v;
    __syncthreads();
    for (int off = 1; off < 1024; off <<= 1) {
        int t = (threadIdx.x >= off) ? s[threadIdx.x - off] : 0;
        __syncthreads();
        s[threadIdx.x] += t;
        __syncthreads();
    }
    if (i < NTOT) g_rowptr[i] = s[threadIdx.x] - v;   // block-local exclusive
    if (threadIdx.x == 1023) g_bsum[blockIdx.x] = s[1023];
}

__global__ void scan2_kernel() {   // parallel scan over 147 block sums
    __shared__ int s[256];
    int t = threadIdx.x;
    int v = (t < SCAN_NB) ? g_bsum[t] : 0;
    s[t] = v;
    __syncthreads();
    for (int off = 1; off < 256; off <<= 1) {
        int x = (t >= off) ? s[t - off] : 0;
        __syncthreads();
        s[t] += x;
        __syncthreads();
    }
    if (t < SCAN_NB) g_bsum[t] = s[t] - v;   // exclusive
}

__global__ void scan3_kernel() {
    int i = blockIdx.x * 1024 + threadIdx.x;
    if (i < NTOT) g_rowptr[i] += g_bsum[i >> 10];
    if (blockIdx.x == 0 && threadIdx.x == 0) g_rowptr[NTOT] = 2 * NUM_E;
}

__global__ void scatter_kernel(const int* __restrict__ edge) {
    int e = blockIdx.x * blockDim.x + threadIdx.x;
    if (e >= NUM_E) return;
    int u = edge[e];
    int it = edge[NUM_E + e];
    int p1 = g_rowptr[it] + atomicAdd(&g_cur[it], 1);
    g_sorted[p1] = u;                                  // src users, grouped by item
    int p2 = g_rowptr[NUM_I + u] + atomicAdd(&g_cur[NUM_I + u], 1);
    g_sorted[p2] = it;                                 // src items, grouped by user
}

// ---------------- softmax aggregation (single pass, first-edge shift) ----------------
// one warp per dst node; lane owns channels 2*lane, 2*lane+1.
// Shift by the first message value per channel: softmax is shift-invariant, so
// this is exact; removes the online-max branch and halves exp count.
__global__ void agg_kernel(const float* __restrict__ xsrc,
                           const float* __restrict__ xdst,
                           int base, int ndst) {
    int warp = threadIdx.x >> 5;
    int node = blockIdx.x * 8 + warp;
    if (node >= ndst) return;
    int lane = threadIdx.x & 31;
    int beg = g_rowptr[base + node];
    int end = g_rowptr[base + node + 1];

    const float2* xs = (const float2*)xsrc;
    float S0 = 0.f, S1 = 0.f, A0 = 0.f, A1 = 0.f;
    float M0 = 0.f, M1 = 0.f;
    float2 v = make_float2(0.f, 0.f);
    int i1 = 0;
    if (beg < end) {
        int s0 = g_sorted[beg];
        v = xs[(size_t)s0 * 32 + lane];
        M0 = fmaxf(v.x, 0.f) + MSG_EPS;
        M1 = fmaxf(v.y, 0.f) + MSG_EPS;
        if (beg + 1 < end) i1 = g_sorted[beg + 1];
    }
    for (int e = beg; e < end; e++) {
        float2 vc = v;
        if (e + 1 < end) v = xs[(size_t)i1 * 32 + lane];   // prefetch gather
        if (e + 2 < end) i1 = g_sorted[e + 2];             // prefetch index
        float m0 = fmaxf(vc.x, 0.f) + MSG_EPS;
        float m1 = fmaxf(vc.y, 0.f) + MSG_EPS;
        float t0 = __expf(m0 - M0);
        float t1 = __expf(m1 - M1);
        S0 += t0; A0 = fmaf(t0, m0, A0);
        S1 += t1; A1 = fmaf(t1, m1, A1);
    }
    float2 xd = ((const float2*)xdst)[(size_t)node * 32 + lane];
    float2 o;
    o.x = ((beg < end) ? A0 / S0 : 0.f) + xd.x;
    o.y = ((beg < end) ? A1 / S1 : 0.f) + xd.y;
    ((float2*)g_z)[(size_t)node * 32 + lane] = o;
}

// ---------------- BN stats finalize (self-resetting for next conv) ----------------
__global__ void stats_kernel(const float* __restrict__ gam,
                             const float* __restrict__ bet, float invN) {
    int c = threadIdx.x;
    float mu  = g_sum[c] * invN;
    float var = fmaxf(g_ssq[c] * invN - mu * mu, 0.f);
    float sc  = gam[c] * rsqrtf(var + BN_EPS);
    g_scale[c] = sc;
    g_shift[c] = bet[c] - mu * sc;
    g_sum[c] = 0.f;           // reset for the next conv's gemm1 accumulation
    g_ssq[c] = 0.f;
}

// ---------------- GEMM1: h = z @ W1 + b1  (+ per-channel sum/sumsq) ----------------
// 256 threads, 128-row x 128-col tile, 8x8 microtile packed as 8x4 f32x2.
// Thread (tx,ty) owns rows ty*8..+7, column pairs {2tx+32j, 2tx+32j+1}, j=0..3.
__global__ __launch_bounds__(256) void gemm1_kernel(const float* __restrict__ W1p,
                                                    const float* __restrict__ b1p, int N) {
    extern __shared__ float smem[];
    float* ws   = smem;                  // 64*128 = 8192
    float* zs   = ws + DIM * DIM2;       // 128*68 = 8704 (pad 68: float4-aligned rows)
    float* sbuf = zs + 128 * 68;         // 128
    float* qbuf = sbuf + DIM2;           // 128
    int tid = threadIdx.x;
    int R0 = blockIdx.x * 128;

    for (int i = tid; i < DIM * DIM2 / 4; i += 256)
        ((float4*)ws)[i] = ((const float4*)W1p)[i];
    for (int i = tid; i < 128 * 16; i += 256) {
        int r = i >> 4, c4 = i & 15;
        float4 v = make_float4(0.f, 0.f, 0.f, 0.f);
        int row = R0 + r;
        if (row < N) v = ((const float4*)g_z)[(size_t)row * 16 + c4];
        *(float4*)&zs[r * 68 + c4 * 4] = v;
    }
    if (tid < DIM2) { sbuf[tid] = 0.f; qbuf[tid] = 0.f; }
    __syncthreads();

    int tx = tid & 15, ty = tid >> 4;
    ull acc[8][4];
#pragma unroll
    for (int i = 0; i < 8; i++)
#pragma unroll
        for (int j = 0; j < 4; j++) acc[i][j] = 0ULL;

#pragma unroll 4
    for (int k = 0; k < DIM; k++) {
        ull a2[8];
#pragma unroll
        for (int i = 0; i < 8; i++) a2[i] = pack2(zs[(ty * 8 + i) * 68 + k]);
        ull w2[4];
#pragma unroll
        for (int j = 0; j < 4; j++) w2[j] = *(const ull*)&ws[k * DIM2 + 2 * tx + 32 * j];
#pragma unroll
        for (int i = 0; i < 8; i++)
#pragma unroll
            for (int j = 0; j < 4; j++) ffma2(acc[i][j], a2[i], w2[j]);
    }

#pragma unroll
    for (int j = 0; j < 4; j++) {
        int c0 = 2 * tx + 32 * j;
        float b0 = b1p[c0], b1v = b1p[c0 + 1];
        float s0 = 0.f, q0 = 0.f, s1 = 0.f, q1 = 0.f;
#pragma unroll
        for (int i = 0; i < 8; i++) {
            int row = R0 + ty * 8 + i;
            float lo, hi;
            unpack2(acc[i][j], lo, hi);
            if (row < N) {
                float h0 = lo + b0, h1 = hi + b1v;
                *(float2*)&g_h[(size_t)row * DIM2 + c0] = make_float2(h0, h1);
                s0 += h0; q0 = fmaf(h0, h0, q0);
                s1 += h1; q1 = fmaf(h1, h1, q1);
            }
        }
        // lanes l and l^16 share the same columns (same tx, adjacent ty)
        s0 += __shfl_xor_sync(0xffffffffu, s0, 16);
        q0 += __shfl_xor_sync(0xffffffffu, q0, 16);
        s1 += __shfl_xor_sync(0xffffffffu, s1, 16);
        q1 += __shfl_xor_sync(0xffffffffu, q1, 16);
        if ((tid & 16) == 0) {
            atomicAdd(&sbuf[c0], s0);     atomicAdd(&qbuf[c0], q0);
            atomicAdd(&sbuf[c0 + 1], s1); atomicAdd(&qbuf[c0 + 1], q1);
        }
    }
    __syncthreads();
    if (tid < DIM2) {
        atomicAdd(&g_sum[tid], sbuf[tid]);
        atomicAdd(&g_ssq[tid], qbuf[tid]);
    }
}

// ---------------- GEMM2: out = relu( relu(scale*h+shift) @ W2 + b2 ) ----------------
// 256 threads, 128-row x 64-col tile, 8x4 microtile packed as 8x2 f32x2.
__global__ __launch_bounds__(256) void gemm2_kernel(const float* __restrict__ W2p,
                                                    const float* __restrict__ b2p,
                                                    float* __restrict__ outp, int N) {
    extern __shared__ float smem[];
    float* ws  = smem;                   // 128*64 = 8192
    float* hs  = ws + DIM2 * DIM;        // 128*132 = 16896 (pad 132: float4-aligned)
    float* ssc = hs + 128 * 132;         // 128
    float* ssh = ssc + DIM2;             // 128
    int tid = threadIdx.x;
    int R0 = blockIdx.x * 128;

    if (tid < DIM2) { ssc[tid] = g_scale[tid]; ssh[tid] = g_shift[tid]; }
    __syncthreads();

    for (int i = tid; i < DIM2 * DIM / 4; i += 256)
        ((float4*)ws)[i] = ((const float4*)W2p)[i];
    for (int i = tid; i < 128 * 32; i += 256) {
        int r = i >> 5, k4 = i & 31;
        float4 v = make_float4(0.f, 0.f, 0.f, 0.f);
        int row = R0 + r;
        if (row < N) v = ((const float4*)g_h)[(size_t)row * 32 + k4];
        int k = k4 * 4;
        float4 o;
        o.x = fmaxf(fmaf(v.x, ssc[k + 0], ssh[k + 0]), 0.f);
        o.y = fmaxf(fmaf(v.y, ssc[k + 1], ssh[k + 1]), 0.f);
        o.z = fmaxf(fmaf(v.z, ssc[k + 2], ssh[k + 2]), 0.f);
        o.w = fmaxf(fmaf(v.w, ssc[k + 3], ssh[k + 3]), 0.f);
        *(float4*)&hs[r * 132 + k] = o;
    }
    __syncthreads();

    int tx = tid & 15, ty = tid >> 4;
    ull acc[8][2];
#pragma unroll
    for (int i = 0; i < 8; i++)
#pragma unroll
        for (int j = 0; j < 2; j++) acc[i][j] = 0ULL;

#pragma unroll 4
    for (int k = 0; k < DIM2; k++) {
        ull a2[8];
#pragma unroll
        for (int i = 0; i < 8; i++) a2[i] = pack2(hs[(ty * 8 + i) * 132 + k]);
        ull w2[2];
#pragma unroll
        for (int j = 0; j < 2; j++) w2[j] = *(const ull*)&ws[k * DIM + 2 * tx + 32 * j];
#pragma unroll
        for (int i = 0; i < 8; i++)
#pragma unroll
            for (int j = 0; j < 2; j++) ffma2(acc[i][j], a2[i], w2[j]);
    }

#pragma unroll
    for (int j = 0; j < 2; j++) {
        int c0 = 2 * tx + 32 * j;
        float b0 = b2p[c0], b1v = b2p[c0 + 1];
#pragma unroll
        for (int i = 0; i < 8; i++) {
            int row = R0 + ty * 8 + i;
            if (row < N) {
                float lo, hi;
                unpack2(acc[i][j], lo, hi);
                *(float2*)&outp[(size_t)row * DIM + c0] =
                    make_float2(fmaxf(lo + b0, 0.f), fmaxf(hi + b1v, 0.f));
            }
        }
    }
}

// ---------------- decoder: 16 lanes per supervision edge, float4 ----------------
__global__ void dec_kernel(const float* __restrict__ fu,
                           const float* __restrict__ fi,
                           const int* __restrict__ pe,
                           float* __restrict__ out) {
    int t = blockIdx.x * blockDim.x + threadIdx.x;
    int g = t >> 4;
    if (g >= NUM_B) return;
    int lane = t & 15;
    int pu = pe[g];
    int pi = pe[NUM_B + g];
    float4 a = ((const float4*)fu)[(size_t)pu * 16 + lane];
    float4 c = ((const float4*)fi)[(size_t)pi * 16 + lane];
    float s = a.x * c.x + a.y * c.y + a.z * c.z + a.w * c.w;
    s += __shfl_xor_sync(0xffffffffu, s, 8);
    s += __shfl_xor_sync(0xffffffffu, s, 4);
    s += __shfl_xor_sync(0xffffffffu, s, 2);
    s += __shfl_xor_sync(0xffffffffu, s, 1);
    if (lane == 0) out[g] = s;
}

// ---------------- host ----------------
extern "C" void kernel_launch(void* const* d_in, const int* in_sizes, int n_in,
                              void* d_out, int out_size) {
    const float* x_user = (const float*)d_in[0];
    const float* x_item = (const float*)d_in[1];
    const float* W1     = (const float*)d_in[2];
    const float* b1     = (const float*)d_in[3];
    const float* gam    = (const float*)d_in[4];
    const float* bet    = (const float*)d_in[5];
    const float* W2     = (const float*)d_in[6];
    const float* b2     = (const float*)d_in[7];
    const int*   edge   = (const int*)d_in[8];
    const int*   pred   = (const int*)d_in[9];
    float*       out    = (float*)d_out;

    const int SM1 = (DIM * DIM2 + 128 * 68 + 2 * DIM2) * 4;       // 68608 B
    const int SM2 = (DIM2 * DIM + 128 * 132 + 2 * DIM2) * 4;      // 101376 B
    cudaFuncSetAttribute(gemm1_kernel, cudaFuncAttributeMaxDynamicSharedMemorySize, SM1);
    cudaFuncSetAttribute(gemm2_kernel, cudaFuncAttributeMaxDynamicSharedMemorySize, SM2);

    float *fu0, *fi0;
    cudaGetSymbolAddress((void**)&fu0, g_fu);
    cudaGetSymbolAddress((void**)&fi0, g_fi);
    float* fu1 = fu0 + (size_t)NUM_U * DIM;
    float* fi1 = fi0 + (size_t)NUM_I * DIM;

    // CSR build (graph fixed across layers)
    zero_kernel<<<(NTOT + 255) / 256, 256>>>();
    hist_kernel<<<(NUM_E + 255) / 256, 256>>>(edge);
    scan1_kernel<<<SCAN_NB, 1024>>>();
    scan2_kernel<<<1, 256>>>();
    scan3_kernel<<<SCAN_NB, 1024>>>();
    scatter_kernel<<<(NUM_E + 255) / 256, 256>>>(edge);

    const float* xu_in = x_user;
    const float* xi_in = x_item;
    for (int l = 0; l < 3; l++) {
        float* xu_out = (l & 1) ? fu1 : fu0;
        float* xi_out = (l & 1) ? fi1 : fi0;

        // conv user->item (et=0), dst = items
        {
            int et = l * 2 + 0;
            agg_kernel<<<(NUM_I + 7) / 8, 256>>>(xu_in, xi_in, 0, NUM_I);
            gemm1_kernel<<<(NUM_I + 127) / 128, 256, SM1>>>(W1 + (size_t)et * DIM * DIM2,
                                                            b1 + (size_t)et * DIM2, NUM_I);
            stats_kernel<<<1, 128>>>(gam + (size_t)et * DIM2, bet + (size_t)et * DIM2,
                                     1.0f / NUM_I);
            gemm2_kernel<<<(NUM_I + 127) / 128, 256, SM2>>>(W2 + (size_t)et * DIM2 * DIM,
                                                            b2 + (size_t)et * DIM, xi_out, NUM_I);
        }
        // conv item->user (et=1), dst = users
        {
            int et = l * 2 + 1;
            agg_kernel<<<(NUM_U + 7) / 8, 256>>>(xi_in, xu_in, NUM_I, NUM_U);
            gemm1_kernel<<<(NUM_U + 127) / 128, 256, SM1>>>(W1 + (size_t)et * DIM * DIM2,
                                                            b1 + (size_t)et * DIM2, NUM_U);
            stats_kernel<<<1, 128>>>(gam + (size_t)et * DIM2, bet + (size_t)et * DIM2,
                                     1.0f / NUM_U);
            gemm2_kernel<<<(NUM_U + 127) / 128, 256, SM2>>>(W2 + (size_t)et * DIM2 * DIM,
                                                            b2 + (size_t)et * DIM, xu_out, NUM_U);
        }
        xu_in = xu_out;
        xi_in = xi_out;
    }

    dec_kernel<<<(NUM_B * 16 + 255) / 256, 256>>>(xu_in, xi_in, pred, out);
}